// round 12
// baseline (speedup 1.0000x reference)
#include <cuda_runtime.h>

#define E_EDGE 8192
#define BATCH  32
#define N_VAR  2048

// scratch: input transposed to [k][b] (1 MB) and llr pre-scaled+transposed to [v][b] (256 KB)
__device__ float g_inputT[E_EDGE * BATCH];
__device__ float g_llrT[N_VAR * BATCH];

__global__ __launch_bounds__(256) void prep_kernel(const float* __restrict__ input,
                                                   const float* __restrict__ llr,
                                                   const float* __restrict__ llr_w) {
    int tid = blockIdx.x * blockDim.x + threadIdx.x;
    if (tid < E_EDGE * BATCH) {
        int b = tid >> 13;           // tid / 8192  (coalesced read along k)
        int k = tid & (E_EDGE - 1);
        g_inputT[k * BATCH + b] = input[tid];
    } else {
        int t = tid - E_EDGE * BATCH;
        if (t < N_VAR * BATCH) {
            int b = t >> 11;         // t / 2048
            int v = t & (N_VAR - 1);
            g_llrT[v * BATCH + b] = llr[t] * llr_w[v];
        }
    }
}

// One warp per output row e_out; lane = batch b.
// Base = R4 (best measured config: 8 independent 128B .cs loads per group,
// 64-reg budget, 4 blocks/SM). Weight is never streamed: mask*weight == 0
// wherever mask == 0 for ANY weight values, so weight is gathered as one
// float4 per hit (~8 hits per row of 8192).
// R12 adds prefetch.global.L2 with an 8KB/warp lead (2 groups ahead): DRAM-side
// MLP is carried by the prefetch engine at zero register cost, demand loads hit L2.
__global__ __launch_bounds__(256, 4) void bp_main_kernel(
    const float* __restrict__ mask,
    const float* __restrict__ weight,
    float* __restrict__ out)
{
    const int warp = threadIdx.x >> 5;          // 0..7
    const int lane = threadIdx.x & 31;          // batch b
    const int row0 = blockIdx.x << 3;           // 8 rows per block
    const int row  = row0 + warp;               // e_out

    const float4* __restrict__ m4 = reinterpret_cast<const float4*>(mask + (size_t)row * E_EDGE);
    const float*  __restrict__ wr = weight + (size_t)row * E_EDGE;
    const char*   rbase = (const char*)m4;

    float acc = 0.0f;

    // prologue: cover groups 0 and 1 (8KB) so the first demand loads hit L2
    asm volatile("prefetch.global.L2 [%0];" :: "l"(rbase + lane * 128));
    asm volatile("prefetch.global.L2 [%0];" :: "l"(rbase + 4096 + lane * 128));

    // 8 groups × (8 chunks × 32 lanes × 4 floats) = 8192
    const int NG = E_EDGE / 1024;
    for (int g = 0; g < NG; ++g) {
        // prefetch group g+2: 4KB = 32 lines, one line per lane, ONE warp instr
        if (g + 2 < NG)
            asm volatile("prefetch.global.L2 [%0];"
                         :: "l"(rbase + (size_t)(g + 2) * 4096 + lane * 128));

        float4 m[8];
        // issue all 8 mask loads back-to-back: 1 KB in flight per warp (R4 pattern)
        #pragma unroll
        for (int it = 0; it < 8; ++it)
            m[it] = __ldcs(&m4[(g * 8 + it) * 32 + lane]);

        #pragma unroll
        for (int it = 0; it < 8; ++it) {
            // integer nz test; <<1 drops sign bit so ±0.0 is skipped (exact)
            unsigned bits = (__float_as_uint(m[it].x) | __float_as_uint(m[it].y) |
                             __float_as_uint(m[it].z) | __float_as_uint(m[it].w)) << 1;
            unsigned ball = __ballot_sync(0xFFFFFFFFu, bits != 0u);

            // rare path: ~8 nonzeros per whole row of 8192
            while (ball) {
                int src = __ffs(ball) - 1;
                ball &= ball - 1;
                float mx = __shfl_sync(0xFFFFFFFFu, m[it].x, src);
                float my = __shfl_sync(0xFFFFFFFFu, m[it].y, src);
                float mz = __shfl_sync(0xFFFFFFFFu, m[it].z, src);
                float mw = __shfl_sync(0xFFFFFFFFu, m[it].w, src);
                const int k0 = (g * 8 + it) * 128 + src * 4;
                const float4 w4 = __ldg(reinterpret_cast<const float4*>(wr + k0)); // one 16B gather
                const float* t = g_inputT + (size_t)k0 * BATCH + lane;             // coalesced
                if (mx != 0.0f) acc = fmaf(mx * w4.x, t[0 * BATCH], acc);
                if (my != 0.0f) acc = fmaf(my * w4.y, t[1 * BATCH], acc);
                if (mz != 0.0f) acc = fmaf(mz * w4.z, t[2 * BATCH], acc);
                if (mw != 0.0f) acc = fmaf(mw * w4.w, t[3 * BATCH], acc);
            }
        }
    }

    // epilogue: llr term (pre-scaled, coalesced) + smem transpose for full-sector stores
    __shared__ float tile[8][33];
    const int v = row & (N_VAR - 1);
    tile[warp][lane] = 0.5f * (g_llrT[v * BATCH + lane] + acc);
    __syncthreads();

    // thread t: b = t>>3 (0..31), el = t&7 -> each 8-thread group writes one
    // full, aligned 32B sector of out[b][row0 .. row0+7]
    const int b  = threadIdx.x >> 3;
    const int el = threadIdx.x & 7;
    out[(size_t)b * E_EDGE + row0 + el] = tile[el][b];
}

extern "C" void kernel_launch(void* const* d_in, const int* in_sizes, int n_in,
                              void* d_out, int out_size) {
    const float* input    = (const float*)d_in[0];  // [32, 8192]
    const float* input_w  = (const float*)d_in[1];  // [8192, 8192]
    const float* mask     = (const float*)d_in[2];  // [8192, 8192]
    const float* llr      = (const float*)d_in[3];  // [32, 2048]
    const float* llr_w    = (const float*)d_in[4];  // [1, 2048]
    // d_in[5] = llr_expander (one-hot of e % N_VAR) — realized via index math
    float* out = (float*)d_out;                     // [32, 8192]

    (void)in_sizes; (void)n_in; (void)out_size;

    const int prep_n = E_EDGE * BATCH + N_VAR * BATCH;
    prep_kernel<<<(prep_n + 255) / 256, 256>>>(input, llr, llr_w);

    // 8192 rows, 8 rows (warps) per 256-thread block
    bp_main_kernel<<<E_EDGE / 8, 256>>>(mask, input_w, out);
}

// round 13
// speedup vs baseline: 1.0360x; 1.0360x over previous
#include <cuda_runtime.h>

#define E_EDGE 8192
#define BATCH  32
#define N_VAR  2048

// scratch: input transposed to [k][b] (1 MB) and llr pre-scaled+transposed to [v][b] (256 KB)
__device__ float g_inputT[E_EDGE * BATCH];
__device__ float g_llrT[N_VAR * BATCH];

__global__ __launch_bounds__(256) void prep_kernel(const float* __restrict__ input,
                                                   const float* __restrict__ llr,
                                                   const float* __restrict__ llr_w) {
    int tid = blockIdx.x * blockDim.x + threadIdx.x;
    if (tid < E_EDGE * BATCH) {
        int b = tid >> 13;           // tid / 8192  (coalesced read along k)
        int k = tid & (E_EDGE - 1);
        g_inputT[k * BATCH + b] = input[tid];
    } else {
        int t = tid - E_EDGE * BATCH;
        if (t < N_VAR * BATCH) {
            int b = t >> 11;         // t / 2048
            int v = t & (N_VAR - 1);
            g_llrT[v * BATCH + b] = llr[t] * llr_w[v];
        }
    }
}

// One warp per output row e_out; lane = batch b.
// Weight is never streamed (mask*weight == 0 wherever mask == 0 for ANY weight);
// it's gathered as one float4 per hit (~8 hits per 8192-wide row).
// R13 KEY: each streamed float4 is consumed IMMEDIATELY into a 1-register nz
// word, so its liveness is a few cycles — ptxas can run an 8-deep load pipeline
// in a ~40-reg budget (high occupancy AND deep MLP, previously mutually
// exclusive). On the rare hit the 16B is RELOADED at a computed address: all
// lanes read the same line (broadcast, cache-resident since just streamed), and
// the shuffles disappear from the hit path entirely.
__global__ __launch_bounds__(256, 6) void bp_main_kernel(
    const float* __restrict__ mask,
    const float* __restrict__ weight,
    float* __restrict__ out)
{
    const int warp = threadIdx.x >> 5;          // 0..7
    const int lane = threadIdx.x & 31;          // batch b
    const int row0 = blockIdx.x << 3;           // 8 rows per block
    const int row  = row0 + warp;               // e_out

    const float4* __restrict__ m4 = reinterpret_cast<const float4*>(mask + (size_t)row * E_EDGE);
    const float*  __restrict__ wr = weight + (size_t)row * E_EDGE;

    float acc = 0.0f;

    // 8 groups × (8 chunks × 32 lanes × 4 floats) = 8192
    const int NG = E_EDGE / 1024;
    for (int g = 0; g < NG; ++g) {
        unsigned nz[8];
        // phase 1: stream 8 chunks; each float4 dies into its nz word at once
        #pragma unroll
        for (int it = 0; it < 8; ++it) {
            float4 m = __ldcs(&m4[(g * 8 + it) * 32 + lane]);
            // <<1 drops the sign bit so ±0.0 registers as zero (exact)
            nz[it] = (__float_as_uint(m.x) | __float_as_uint(m.y) |
                      __float_as_uint(m.z) | __float_as_uint(m.w)) << 1;
        }

        // phase 2: ballots + rare hit path (reload values from cache)
        #pragma unroll
        for (int it = 0; it < 8; ++it) {
            unsigned ball = __ballot_sync(0xFFFFFFFFu, nz[it] != 0u);

            // ~8 nonzeros per whole row of 8192
            while (ball) {
                int src = __ffs(ball) - 1;
                ball &= ball - 1;
                const int k0 = (g * 8 + it) * 128 + src * 4;
                // broadcast reloads: every lane reads the same 16B (L1/L2 hit)
                const float4 mv = __ldg(&m4[(g * 8 + it) * 32 + src]);
                const float4 w4 = __ldg(reinterpret_cast<const float4*>(wr + k0));
                const float* t  = g_inputT + (size_t)k0 * BATCH + lane;  // coalesced
                if (mv.x != 0.0f) acc = fmaf(mv.x * w4.x, t[0 * BATCH], acc);
                if (mv.y != 0.0f) acc = fmaf(mv.y * w4.y, t[1 * BATCH], acc);
                if (mv.z != 0.0f) acc = fmaf(mv.z * w4.z, t[2 * BATCH], acc);
                if (mv.w != 0.0f) acc = fmaf(mv.w * w4.w, t[3 * BATCH], acc);
            }
        }
    }

    // epilogue: llr term (pre-scaled, coalesced) + smem transpose for full-sector stores
    __shared__ float tile[8][33];
    tile[warp][lane] = 0.5f * (g_llrT[(row & (N_VAR - 1)) * BATCH + lane] + acc);
    __syncthreads();

    // thread t: b = t>>3 (0..31), el = t&7 -> each 8-thread group writes one
    // full, aligned 32B sector of out[b][row0 .. row0+7]
    const int b  = threadIdx.x >> 3;
    const int el = threadIdx.x & 7;
    out[(size_t)b * E_EDGE + row0 + el] = tile[el][b];
}

extern "C" void kernel_launch(void* const* d_in, const int* in_sizes, int n_in,
                              void* d_out, int out_size) {
    const float* input    = (const float*)d_in[0];  // [32, 8192]
    const float* input_w  = (const float*)d_in[1];  // [8192, 8192]
    const float* mask     = (const float*)d_in[2];  // [8192, 8192]
    const float* llr      = (const float*)d_in[3];  // [32, 2048]
    const float* llr_w    = (const float*)d_in[4];  // [1, 2048]
    // d_in[5] = llr_expander (one-hot of e % N_VAR) — realized via index math
    float* out = (float*)d_out;                     // [32, 8192]

    (void)in_sizes; (void)n_in; (void)out_size;

    const int prep_n = E_EDGE * BATCH + N_VAR * BATCH;
    prep_kernel<<<(prep_n + 255) / 256, 256>>>(input, llr, llr_w);

    // 8192 rows, 8 rows (warps) per 256-thread block
    bp_main_kernel<<<E_EDGE / 8, 256>>>(mask, input_w, out);
}